// round 1
// baseline (speedup 1.0000x reference)
#include <cuda_runtime.h>

#define B_   32
#define CIN  96
#define HH   56
#define WW   56
#define HW   3136      // 56*56
#define P0   384
#define P1   72
#define EPS  1e-5f

// Scratch: expand output and depthwise output (NCHW, fp32).
// __device__ globals per harness rules (no cudaMalloc allowed).
__device__ float g_h1[B_ * P0 * HW];   // 154 MB
__device__ float g_h2[B_ * P0 * HW];   // 154 MB

// ---------------------------------------------------------------------------
// Kernel 1: 1x1 expand conv (96 -> 384) + BN1 + ReLU6, written to g_h1.
// GEMM per image: C[384 x 3136] = We[384 x 96] * X[96 x 3136]
// Block tile: 128 out-channels x 64 pixels, K chunk 32. 256 threads,
// per-thread register tile 8x4.
// grid = (3136/64 = 49, 384/128 = 3, 32), block = 256
// ---------------------------------------------------------------------------
__global__ __launch_bounds__(256)
void expand_kernel(const float* __restrict__ x,
                   const float* __restrict__ we,
                   const float* __restrict__ g1, const float* __restrict__ b1,
                   const float* __restrict__ m1, const float* __restrict__ v1)
{
    __shared__ float As[32][132];   // [k][m], stride 132 keeps rows 16B aligned
    __shared__ float Bs[32][68];    // [k][p]

    const int tid   = threadIdx.x;
    const int nBase = blockIdx.x * 64;     // pixel base
    const int mBase = blockIdx.y * 128;    // expanded-channel base
    const int b     = blockIdx.z;

    const int tm = (tid >> 4) * 8;   // 0..120 : channel offset within tile
    const int tp = (tid & 15) * 4;   // 0..60  : pixel offset within tile

    float acc[8][4];
    #pragma unroll
    for (int i = 0; i < 8; i++)
        #pragma unroll
        for (int j = 0; j < 4; j++) acc[i][j] = 0.f;

    for (int kc = 0; kc < CIN; kc += 32) {
        __syncthreads();
        // Load A tile: As[k][m] = we[(mBase+m)*96 + kc + k]
        #pragma unroll
        for (int t = tid; t < 128 * 32; t += 256) {
            int m = t >> 5, k = t & 31;
            As[k][m] = we[(mBase + m) * CIN + kc + k];
        }
        // Load B tile: Bs[k][p] = x[b][kc+k][nBase+p]
        #pragma unroll
        for (int t = tid; t < 32 * 64; t += 256) {
            int k = t >> 6, p = t & 63;
            Bs[k][p] = x[(b * CIN + kc + k) * HW + nBase + p];
        }
        __syncthreads();

        #pragma unroll 8
        for (int k = 0; k < 32; k++) {
            float4 a0 = *(const float4*)&As[k][tm];
            float4 a1 = *(const float4*)&As[k][tm + 4];
            float4 bb = *(const float4*)&Bs[k][tp];
            float ar[8] = {a0.x, a0.y, a0.z, a0.w, a1.x, a1.y, a1.z, a1.w};
            float br[4] = {bb.x, bb.y, bb.z, bb.w};
            #pragma unroll
            for (int i = 0; i < 8; i++)
                #pragma unroll
                for (int j = 0; j < 4; j++)
                    acc[i][j] = fmaf(ar[i], br[j], acc[i][j]);
        }
    }

    // Epilogue: BN1 + ReLU6, float4 stores
    #pragma unroll
    for (int i = 0; i < 8; i++) {
        int o = mBase + tm + i;
        float sc = g1[o] * rsqrtf(v1[o] + EPS);
        float sh = b1[o] - m1[o] * sc;
        float4 v;
        v.x = fminf(fmaxf(acc[i][0] * sc + sh, 0.f), 6.f);
        v.y = fminf(fmaxf(acc[i][1] * sc + sh, 0.f), 6.f);
        v.z = fminf(fmaxf(acc[i][2] * sc + sh, 0.f), 6.f);
        v.w = fminf(fmaxf(acc[i][3] * sc + sh, 0.f), 6.f);
        *(float4*)&g_h1[(b * P0 + o) * HW + nBase + tp] = v;
    }
}

// ---------------------------------------------------------------------------
// Kernel 2: 3x3 depthwise conv (pad 1, stride 1) + BN2 + ReLU6 -> g_h2.
// Block: one (batch, channel, 8-row stripe). Smem tile 10x58 with halo.
// grid = (56/8 = 7, 384, 32), block = (56, 8)
// ---------------------------------------------------------------------------
__global__ __launch_bounds__(448)
void dw_kernel(const float* __restrict__ dw,
               const float* __restrict__ g2, const float* __restrict__ b2,
               const float* __restrict__ m2, const float* __restrict__ v2)
{
    __shared__ float s[10][58];

    const int tx  = threadIdx.x;          // 0..55
    const int ty  = threadIdx.y;          // 0..7
    const int tid = ty * 56 + tx;         // 0..447
    const int y0  = blockIdx.x * 8;
    const int c   = blockIdx.y;
    const int b   = blockIdx.z;

    const float* src = g_h1 + (b * P0 + c) * HW;

    for (int t = tid; t < 10 * 58; t += 448) {
        int r = t / 58, q = t % 58;
        int y = y0 - 1 + r, xx = q - 1;
        float v = 0.f;
        if (y >= 0 && y < HH && xx >= 0 && xx < WW) v = src[y * WW + xx];
        s[r][q] = v;
    }
    __syncthreads();

    float w[9];
    #pragma unroll
    for (int i = 0; i < 9; i++) w[i] = dw[c * 9 + i];

    float acc = 0.f;
    #pragma unroll
    for (int dy = 0; dy < 3; dy++)
        #pragma unroll
        for (int dx = 0; dx < 3; dx++)
            acc = fmaf(w[dy * 3 + dx], s[ty + dy][tx + dx], acc);

    float sc = g2[c] * rsqrtf(v2[c] + EPS);
    float sh = b2[c] - m2[c] * sc;
    g_h2[(b * P0 + c) * HW + (y0 + ty) * WW + tx] =
        fminf(fmaxf(acc * sc + sh, 0.f), 6.f);
}

// ---------------------------------------------------------------------------
// Kernel 3: 1x1 project conv (384 -> 72) + BN3 + scatter(idx) + residual.
// out was pre-filled with x (memcpy); this kernel overwrites the 72
// preserved channels with x + bn3(proj).
// GEMM per image: P[72 x 3136] = Wp[72 x 384] * H2[384 x 3136]
// Block tile: 72 channels x 64 pixels, K chunk 32. 288 threads,
// per-thread tile 8x2.
// grid = (49, 1, 32), block = 288
// ---------------------------------------------------------------------------
__global__ __launch_bounds__(288)
void project_kernel(const float* __restrict__ x,
                    const float* __restrict__ wp,
                    const float* __restrict__ g3, const float* __restrict__ b3,
                    const float* __restrict__ m3, const float* __restrict__ v3,
                    const int* __restrict__ idx,
                    float* __restrict__ out)
{
    __shared__ float Ws[32][76];   // [k][o]
    __shared__ float Hs[32][68];   // [k][p]

    const int tid = threadIdx.x;
    const int p0  = blockIdx.x * 64;
    const int b   = blockIdx.z;

    const int tm = (tid >> 5) * 8;   // 0..64 : channel offset (9 groups * 8 = 72)
    const int tp = (tid & 31) * 2;   // 0..62 : pixel offset

    float acc[8][2];
    #pragma unroll
    for (int i = 0; i < 8; i++) { acc[i][0] = 0.f; acc[i][1] = 0.f; }

    for (int k0 = 0; k0 < P0; k0 += 32) {
        __syncthreads();
        #pragma unroll
        for (int t = tid; t < 72 * 32; t += 288) {
            int o = t >> 5, k = t & 31;
            Ws[k][o] = wp[o * P0 + k0 + k];
        }
        for (int t = tid; t < 32 * 64; t += 288) {
            int k = t >> 6, p = t & 63;
            Hs[k][p] = g_h2[(b * P0 + k0 + k) * HW + p0 + p];
        }
        __syncthreads();

        #pragma unroll 8
        for (int k = 0; k < 32; k++) {
            float4 a0 = *(const float4*)&Ws[k][tm];
            float4 a1 = *(const float4*)&Ws[k][tm + 4];
            float2 bb = *(const float2*)&Hs[k][tp];
            float ar[8] = {a0.x, a0.y, a0.z, a0.w, a1.x, a1.y, a1.z, a1.w};
            #pragma unroll
            for (int i = 0; i < 8; i++) {
                acc[i][0] = fmaf(ar[i], bb.x, acc[i][0]);
                acc[i][1] = fmaf(ar[i], bb.y, acc[i][1]);
            }
        }
    }

    #pragma unroll
    for (int i = 0; i < 8; i++) {
        int o = tm + i;
        float sc = g3[o] * rsqrtf(v3[o] + EPS);
        float sh = b3[o] - m3[o] * sc;
        int co = idx[o];
        int base = (b * CIN + co) * HW + p0 + tp;
        out[base]     = x[base]     + (acc[i][0] * sc + sh);
        out[base + 1] = x[base + 1] + (acc[i][1] * sc + sh);
    }
}

// ---------------------------------------------------------------------------
extern "C" void kernel_launch(void* const* d_in, const int* in_sizes, int n_in,
                              void* d_out, int out_size)
{
    const float* x  = (const float*)d_in[0];
    const float* we = (const float*)d_in[1];
    const float* dw = (const float*)d_in[2];
    const float* wp = (const float*)d_in[3];
    const float* g1 = (const float*)d_in[4];
    const float* b1 = (const float*)d_in[5];
    const float* m1 = (const float*)d_in[6];
    const float* v1 = (const float*)d_in[7];
    const float* g2 = (const float*)d_in[8];
    const float* b2 = (const float*)d_in[9];
    const float* m2 = (const float*)d_in[10];
    const float* v2 = (const float*)d_in[11];
    const float* g3 = (const float*)d_in[12];
    const float* b3 = (const float*)d_in[13];
    const float* m3 = (const float*)d_in[14];
    const float* v3 = (const float*)d_in[15];
    const int*   idx = (const int*)d_in[16];
    float* out = (float*)d_out;

    // Residual identity for all channels (preserved ones are overwritten by
    // project_kernel).
    cudaMemcpyAsync(out, x, (size_t)B_ * CIN * HW * sizeof(float),
                    cudaMemcpyDeviceToDevice, 0);

    {
        dim3 grid(HW / 64, P0 / 128, B_);   // (49, 3, 32)
        expand_kernel<<<grid, 256>>>(x, we, g1, b1, m1, v1);
    }
    {
        dim3 grid(HH / 8, P0, B_);          // (7, 384, 32)
        dim3 block(WW, 8);
        dw_kernel<<<grid, block>>>(dw, g2, b2, m2, v2);
    }
    {
        dim3 grid(HW / 64, 1, B_);          // (49, 1, 32)
        project_kernel<<<grid, 288>>>(x, wp, g3, b3, m3, v3, idx, out);
    }
}